// round 7
// baseline (speedup 1.0000x reference)
#include <cuda_runtime.h>
#include <cuda_bf16.h>
#include <math_constants.h>

#define Bq 16
#define Nq 2048
#define Dq 256

// ---------------- scratch (static device globals; no runtime allocation) ----
__device__ float g_si[Bq * Nq];
__device__ float g_sj[Bq * Nq];
__device__ float g_a[Bq * Nq];   // normalized row term
__device__ float g_c[Bq * Nq];   // normalized col term
__device__ float g_Mpart[4 * Bq * Nq];
__device__ float g_Spart[4 * Bq * Nq];
__device__ float g_M[Bq * Nq];
__device__ float g_Zi[Bq * Nq];  // 1/Z per column
__device__ __nv_bfloat16 g_xbf[(size_t)Bq * Nq * Dq];
__device__ __nv_bfloat16 g_P[(size_t)Bq * Nq * Nq];

__device__ __forceinline__ float sigf(float v) {
    return 1.0f / (1.0f + __expf(-v));
}

// ---------------- K1: s_i, s_j projections + bf16 copy of x ----------------
// one warp per (b,n) row; block = 8 warps
__global__ void __launch_bounds__(256) k_proj(const float* __restrict__ x,
                                              const float* __restrict__ w) {
    __shared__ float ws[2 * Dq];
    for (int t = threadIdx.x; t < 2 * Dq; t += blockDim.x) ws[t] = w[t];
    __syncthreads();
    int warp = threadIdx.x >> 5, lane = threadIdx.x & 31;
    size_t row = (size_t)blockIdx.x * 8 + warp;   // < Bq*Nq
    const float4* xr = (const float4*)(x + row * Dq);
    float sj = 0.f, si = 0.f;
#pragma unroll
    for (int k = 0; k < 2; k++) {
        float4 v = xr[k * 32 + lane];
        int e = (k * 32 + lane) * 4;
        sj += v.x * ws[e] + v.y * ws[e + 1] + v.z * ws[e + 2] + v.w * ws[e + 3];
        si += v.x * ws[Dq + e] + v.y * ws[Dq + e + 1] + v.z * ws[Dq + e + 2] + v.w * ws[Dq + e + 3];
        __nv_bfloat162 p0 = __floats2bfloat162_rn(v.x, v.y);
        __nv_bfloat162 p1 = __floats2bfloat162_rn(v.z, v.w);
        *(__nv_bfloat162*)(g_xbf + row * Dq + e)     = p0;
        *(__nv_bfloat162*)(g_xbf + row * Dq + e + 2) = p1;
    }
#pragma unroll
    for (int o = 16; o; o >>= 1) {
        sj += __shfl_xor_sync(0xffffffffu, sj, o);
        si += __shfl_xor_sync(0xffffffffu, si, o);
    }
    if (lane == 0) { g_sj[row] = sj; g_si[row] = si; }
}

// ---------------- K2: per-batch LN stats (separable!) + normalize ----------
__global__ void __launch_bounds__(1024) k_stats() {
    int b = blockIdx.x;
    const float* si = g_si + b * Nq;
    const float* sj = g_sj + b * Nq;
    float s1 = 0, q1 = 0, s2 = 0, q2 = 0;
    for (int i = threadIdx.x; i < Nq; i += 1024) {
        float u = si[i], v = sj[i];
        s1 += u; q1 += u * u; s2 += v; q2 += v * v;
    }
    __shared__ float red[4][32];
    __shared__ float bc[3];
    int w = threadIdx.x >> 5, lane = threadIdx.x & 31;
#pragma unroll
    for (int o = 16; o; o >>= 1) {
        s1 += __shfl_xor_sync(~0u, s1, o);
        q1 += __shfl_xor_sync(~0u, q1, o);
        s2 += __shfl_xor_sync(~0u, s2, o);
        q2 += __shfl_xor_sync(~0u, q2, o);
    }
    if (lane == 0) { red[0][w] = s1; red[1][w] = q1; red[2][w] = s2; red[3][w] = q2; }
    __syncthreads();
    if (threadIdx.x < 32) {
        float v0 = red[0][lane], v1 = red[1][lane], v2 = red[2][lane], v3 = red[3][lane];
#pragma unroll
        for (int o = 16; o; o >>= 1) {
            v0 += __shfl_xor_sync(~0u, v0, o);
            v1 += __shfl_xor_sync(~0u, v1, o);
            v2 += __shfl_xor_sync(~0u, v2, o);
            v3 += __shfl_xor_sync(~0u, v3, o);
        }
        if (lane == 0) {
            float mi = v0 / (float)Nq, mj = v2 / (float)Nq;
            float var = (v1 / (float)Nq - mi * mi) + (v3 / (float)Nq - mj * mj);
            bc[0] = mi; bc[1] = mj; bc[2] = rsqrtf(var + 1e-14f);
        }
    }
    __syncthreads();
    float mi = bc[0], mj = bc[1], inv = bc[2];
    for (int i = threadIdx.x; i < Nq; i += 1024) {
        g_a[b * Nq + i] = (si[i] - mi) * inv;
        g_c[b * Nq + i] = (sj[i] - mj) * inv;
    }
}

// ---------------- K3: per-column online max/sum over an i-chunk ------------
// blockIdx.x = jt*64 + isc*16 + b   (b fastest -> gamma tile L2-shared across batches)
__global__ void __launch_bounds__(256) k_colstats(const float* __restrict__ gamma,
                                                  const float* __restrict__ beta) {
    int b   = blockIdx.x & 15;
    int isc = (blockIdx.x >> 4) & 3;
    int jt  = blockIdx.x >> 6;
    int j = jt * 256 + threadIdx.x;
    __shared__ float ash[512];
    ash[threadIdx.x]       = g_a[b * Nq + isc * 512 + threadIdx.x];
    ash[threadIdx.x + 256] = g_a[b * Nq + isc * 512 + threadIdx.x + 256];
    __syncthreads();
    float cj = g_c[b * Nq + j];
    const float* gp = gamma + (size_t)(isc * 512) * Nq + j;
    const float* bp = beta  + (size_t)(isc * 512) * Nq + j;
    float m = -CUDART_INF_F, s = 0.f;
#pragma unroll 4
    for (int i = 0; i < 512; i++) {
        float g  = gp[(size_t)i * Nq];
        float bt = bp[(size_t)i * Nq];
        float v = fmaf(ash[i] + cj, g, bt);
        v = v >= 0.f ? v : 0.2f * v;
        if (v > m) { s *= __expf(m - v); m = v; }
        s += __expf(v - m);
    }
    int idx = (isc * 16 + b) * Nq + j;
    g_Mpart[idx] = m;
    g_Spart[idx] = s;
}

// ---------------- K3b: combine i-chunk partials ----------------------------
__global__ void __launch_bounds__(256) k_combine() {
    int idx = blockIdx.x * 256 + threadIdx.x;   // = b*Nq + j
    int b = idx >> 11, j = idx & (Nq - 1);
    float mv[4], sv[4];
#pragma unroll
    for (int p = 0; p < 4; p++) {
        mv[p] = g_Mpart[(p * 16 + b) * Nq + j];
        sv[p] = g_Spart[(p * 16 + b) * Nq + j];
    }
    float m = fmaxf(fmaxf(mv[0], mv[1]), fmaxf(mv[2], mv[3]));
    float s = 0.f;
#pragma unroll
    for (int p = 0; p < 4; p++) s += sv[p] * __expf(mv[p] - m);
    g_M[idx]  = m;
    g_Zi[idx] = 1.0f / s;
}

// ---------------- K4: write normalized softmax matrix P (bf16) -------------
__global__ void __launch_bounds__(256) k_pmat(const float* __restrict__ gamma,
                                              const float* __restrict__ beta) {
    int b   = blockIdx.x & 15;
    int isc = (blockIdx.x >> 4) & 3;
    int jt  = blockIdx.x >> 6;
    int j = jt * 256 + threadIdx.x;
    __shared__ float ash[512];
    ash[threadIdx.x]       = g_a[b * Nq + isc * 512 + threadIdx.x];
    ash[threadIdx.x + 256] = g_a[b * Nq + isc * 512 + threadIdx.x + 256];
    __syncthreads();
    float cj = g_c[b * Nq + j];
    float Mj = g_M[b * Nq + j];
    float Zi = g_Zi[b * Nq + j];
    const float* gp = gamma + (size_t)(isc * 512) * Nq + j;
    const float* bp = beta  + (size_t)(isc * 512) * Nq + j;
    __nv_bfloat16* pp = g_P + ((size_t)b * Nq + isc * 512) * Nq + j;
#pragma unroll 4
    for (int i = 0; i < 512; i++) {
        float g  = gp[(size_t)i * Nq];
        float bt = bp[(size_t)i * Nq];
        float v = fmaf(ash[i] + cj, g, bt);
        v = v >= 0.f ? v : 0.2f * v;
        float e = __expf(v - Mj) * Zi;
        pp[(size_t)i * Nq] = __float2bfloat16(e);
    }
}

// ---------------- K5: batched GEMM out = P @ xbf, sigmoid epilogue ---------
// block tile 128x128, BK=32, 8 warps (4x2), mma.sync m16n8k16 bf16
#define PSTR 40    // padded smem stride for P tile rows (32 used + 8 pad) -> 80B
#define XSTR 136   // padded smem stride for x tile rows (128 used + 8 pad) -> 272B
__global__ void __launch_bounds__(256) k_gemm(float* __restrict__ out) {
    __shared__ __align__(16) __nv_bfloat16 ps[2][128 * PSTR];
    __shared__ __align__(16) __nv_bfloat16 xs[2][32 * XSTR];

    int b  = blockIdx.z;
    int m0 = blockIdx.x * 128;
    int n0 = blockIdx.y * 128;
    const __nv_bfloat16* Pg = g_P   + (size_t)b * Nq * Nq;
    const __nv_bfloat16* Xg = g_xbf + (size_t)b * Nq * Dq;

    int tid = threadIdx.x, lane = tid & 31, warp = tid >> 5;
    int wm = warp >> 1, wn = warp & 1;

    // loader indices
    int li1 = tid + 256;
    int rp0 = tid >> 2,  cp0 = (tid & 3) * 8;
    int rp1 = li1 >> 2,  cp1 = (li1 & 3) * 8;
    int rx0 = tid >> 4,  cx0 = (tid & 15) * 8;
    int rx1 = li1 >> 4,  cx1 = (li1 & 15) * 8;

    // ldmatrix lane address components
    int lr = (lane & 7) + ((lane >> 3) & 1) * 8;
    int lc = (lane >> 4) * 8;

    float acc[2][8][4];
#pragma unroll
    for (int mt = 0; mt < 2; mt++)
#pragma unroll
        for (int nt = 0; nt < 8; nt++)
#pragma unroll
            for (int q = 0; q < 4; q++) acc[mt][nt][q] = 0.f;

    // prologue: tile 0 -> buffer 0
    {
        uint4 pa = *(const uint4*)(Pg + (size_t)(m0 + rp0) * Nq + cp0);
        uint4 pb = *(const uint4*)(Pg + (size_t)(m0 + rp1) * Nq + cp1);
        uint4 xa = *(const uint4*)(Xg + (size_t)rx0 * Dq + n0 + cx0);
        uint4 xb = *(const uint4*)(Xg + (size_t)rx1 * Dq + n0 + cx1);
        *(uint4*)&ps[0][rp0 * PSTR + cp0] = pa;
        *(uint4*)&ps[0][rp1 * PSTR + cp1] = pb;
        *(uint4*)&xs[0][rx0 * XSTR + cx0] = xa;
        *(uint4*)&xs[0][rx1 * XSTR + cx1] = xb;
    }
    __syncthreads();

    for (int kt = 0; kt < Nq / 32; kt++) {
        int cur = kt & 1;
        bool more = (kt + 1) < (Nq / 32);
        uint4 pa, pb, xa, xb;
        if (more) {
            int kb = (kt + 1) * 32;
            pa = *(const uint4*)(Pg + (size_t)(m0 + rp0) * Nq + kb + cp0);
            pb = *(const uint4*)(Pg + (size_t)(m0 + rp1) * Nq + kb + cp1);
            xa = *(const uint4*)(Xg + (size_t)(kb + rx0) * Dq + n0 + cx0);
            xb = *(const uint4*)(Xg + (size_t)(kb + rx1) * Dq + n0 + cx1);
        }
#pragma unroll
        for (int ks = 0; ks < 2; ks++) {
            int kk = ks * 16;
            unsigned af[2][4];
#pragma unroll
            for (int mt = 0; mt < 2; mt++) {
                unsigned addr = (unsigned)__cvta_generic_to_shared(
                    &ps[cur][(wm * 32 + mt * 16 + lr) * PSTR + kk + lc]);
                asm volatile("ldmatrix.sync.aligned.m8n8.x4.shared.b16 {%0,%1,%2,%3}, [%4];"
                             : "=r"(af[mt][0]), "=r"(af[mt][1]), "=r"(af[mt][2]), "=r"(af[mt][3])
                             : "r"(addr));
            }
            unsigned bfr[8][2];
#pragma unroll
            for (int ng = 0; ng < 4; ng++) {
                unsigned addr = (unsigned)__cvta_generic_to_shared(
                    &xs[cur][(kk + lr) * XSTR + wn * 64 + ng * 16 + lc]);
                unsigned r0, r1, r2, r3;
                asm volatile("ldmatrix.sync.aligned.m8n8.x4.trans.shared.b16 {%0,%1,%2,%3}, [%4];"
                             : "=r"(r0), "=r"(r1), "=r"(r2), "=r"(r3)
                             : "r"(addr));
                bfr[2 * ng][0] = r0; bfr[2 * ng][1] = r1;
                bfr[2 * ng + 1][0] = r2; bfr[2 * ng + 1][1] = r3;
            }
#pragma unroll
            for (int mt = 0; mt < 2; mt++)
#pragma unroll
                for (int nt = 0; nt < 8; nt++)
                    asm volatile("mma.sync.aligned.m16n8k16.row.col.f32.bf16.bf16.f32 "
                                 "{%0,%1,%2,%3}, {%4,%5,%6,%7}, {%8,%9}, {%0,%1,%2,%3};"
                                 : "+f"(acc[mt][nt][0]), "+f"(acc[mt][nt][1]),
                                   "+f"(acc[mt][nt][2]), "+f"(acc[mt][nt][3])
                                 : "r"(af[mt][0]), "r"(af[mt][1]), "r"(af[mt][2]), "r"(af[mt][3]),
                                   "r"(bfr[nt][0]), "r"(bfr[nt][1]));
        }
        if (more) {
            // safe without an extra barrier: buffer `nxt` was last READ in
            // iteration kt-1, whose end-of-loop __syncthreads already ordered
            // those reads before these writes.
            int nxt = cur ^ 1;
            *(uint4*)&ps[nxt][rp0 * PSTR + cp0] = pa;
            *(uint4*)&ps[nxt][rp1 * PSTR + cp1] = pb;
            *(uint4*)&xs[nxt][rx0 * XSTR + cx0] = xa;
            *(uint4*)&xs[nxt][rx1 * XSTR + cx1] = xb;
        }
        __syncthreads();
    }

    // epilogue: sigmoid + store
#pragma unroll
    for (int mt = 0; mt < 2; mt++) {
        int row = m0 + wm * 32 + mt * 16 + (lane >> 2);
#pragma unroll
        for (int nt = 0; nt < 8; nt++) {
            int col = n0 + wn * 64 + nt * 8 + (lane & 3) * 2;
            float2 v0 = { sigf(acc[mt][nt][0]), sigf(acc[mt][nt][1]) };
            float2 v1 = { sigf(acc[mt][nt][2]), sigf(acc[mt][nt][3]) };
            *(float2*)(out + ((size_t)b * Nq + row)     * Dq + col) = v0;
            *(float2*)(out + ((size_t)b * Nq + row + 8) * Dq + col) = v1;
        }
    }
}

// ---------------- launch ---------------------------------------------------
extern "C" void kernel_launch(void* const* d_in, const int* in_sizes, int n_in,
                              void* d_out, int out_size) {
    const float* x     = (const float*)d_in[0];
    const float* w     = (const float*)d_in[1];
    const float* gamma = (const float*)d_in[2];
    const float* beta  = (const float*)d_in[3];
    float* out = (float*)d_out;

    k_proj<<<Bq * Nq / 8, 256>>>(x, w);
    k_stats<<<Bq, 1024>>>();
    k_colstats<<<512, 256>>>(gamma, beta);
    k_combine<<<Bq * Nq / 256, 256>>>();
    k_pmat<<<512, 256>>>(gamma, beta);
    dim3 g5(Nq / 128, Dq / 128, Bq);
    k_gemm<<<g5, 256>>>(out);
}

// round 9
// speedup vs baseline: 1.3124x; 1.3124x over previous
#include <cuda_runtime.h>
#include <cuda_bf16.h>
#include <math_constants.h>

#define Bq 16
#define Nq 2048
#define Dq 256

// ---------------- scratch (static device globals; no runtime allocation) ----
__device__ float g_si[Bq * Nq];
__device__ float g_sj[Bq * Nq];
__device__ float g_a[Bq * Nq];   // normalized row term
__device__ float g_c[Bq * Nq];   // normalized col term
__device__ float g_Spart[4 * Bq * Nq];
__device__ float g_Zi[Bq * Nq];  // 1/Z per column
__device__ float g_amax[Bq];     // per-batch max |a_i|
__device__ int   g_gmax_i;       // max |gamma| as int bits (positive floats)
__device__ int   g_bmax_i;       // max |beta|  as int bits
__device__ __nv_bfloat16 g_xbf[(size_t)Bq * Nq * Dq];
__device__ __nv_bfloat16 g_P[(size_t)Bq * Nq * Nq];

__device__ __forceinline__ float sigf(float v) {
    return 1.0f / (1.0f + __expf(-v));
}

// ---------------- K1: s_i, s_j projections + bf16 copy of x ----------------
// one warp per (b,n) row; block = 8 warps
__global__ void __launch_bounds__(256) k_proj(const float* __restrict__ x,
                                              const float* __restrict__ w) {
    __shared__ float ws[2 * Dq];
    for (int t = threadIdx.x; t < 2 * Dq; t += blockDim.x) ws[t] = w[t];
    __syncthreads();
    int warp = threadIdx.x >> 5, lane = threadIdx.x & 31;
    size_t row = (size_t)blockIdx.x * 8 + warp;   // < Bq*Nq
    const float4* xr = (const float4*)(x + row * Dq);
    float sj = 0.f, si = 0.f;
#pragma unroll
    for (int k = 0; k < 2; k++) {
        float4 v = xr[k * 32 + lane];
        int e = (k * 32 + lane) * 4;
        sj += v.x * ws[e] + v.y * ws[e + 1] + v.z * ws[e + 2] + v.w * ws[e + 3];
        si += v.x * ws[Dq + e] + v.y * ws[Dq + e + 1] + v.z * ws[Dq + e + 2] + v.w * ws[Dq + e + 3];
        __nv_bfloat162 p0 = __floats2bfloat162_rn(v.x, v.y);
        __nv_bfloat162 p1 = __floats2bfloat162_rn(v.z, v.w);
        *(__nv_bfloat162*)(g_xbf + row * Dq + e)     = p0;
        *(__nv_bfloat162*)(g_xbf + row * Dq + e + 2) = p1;
    }
#pragma unroll
    for (int o = 16; o; o >>= 1) {
        sj += __shfl_xor_sync(0xffffffffu, sj, o);
        si += __shfl_xor_sync(0xffffffffu, si, o);
    }
    if (lane == 0) { g_sj[row] = sj; g_si[row] = si; }
}

// ---------------- K2: per-batch LN stats (separable!) + normalize + amax ----
__global__ void __launch_bounds__(1024) k_stats() {
    int b = blockIdx.x;
    const float* si = g_si + b * Nq;
    const float* sj = g_sj + b * Nq;
    float s1 = 0, q1 = 0, s2 = 0, q2 = 0;
    for (int i = threadIdx.x; i < Nq; i += 1024) {
        float u = si[i], v = sj[i];
        s1 += u; q1 += u * u; s2 += v; q2 += v * v;
    }
    __shared__ float red[4][32];
    __shared__ float bc[3];
    int w = threadIdx.x >> 5, lane = threadIdx.x & 31;
#pragma unroll
    for (int o = 16; o; o >>= 1) {
        s1 += __shfl_xor_sync(~0u, s1, o);
        q1 += __shfl_xor_sync(~0u, q1, o);
        s2 += __shfl_xor_sync(~0u, s2, o);
        q2 += __shfl_xor_sync(~0u, q2, o);
    }
    if (lane == 0) { red[0][w] = s1; red[1][w] = q1; red[2][w] = s2; red[3][w] = q2; }
    __syncthreads();
    if (threadIdx.x < 32) {
        float v0 = red[0][lane], v1 = red[1][lane], v2 = red[2][lane], v3 = red[3][lane];
#pragma unroll
        for (int o = 16; o; o >>= 1) {
            v0 += __shfl_xor_sync(~0u, v0, o);
            v1 += __shfl_xor_sync(~0u, v1, o);
            v2 += __shfl_xor_sync(~0u, v2, o);
            v3 += __shfl_xor_sync(~0u, v3, o);
        }
        if (lane == 0) {
            float mi = v0 / (float)Nq, mj = v2 / (float)Nq;
            float var = (v1 / (float)Nq - mi * mi) + (v3 / (float)Nq - mj * mj);
            bc[0] = mi; bc[1] = mj; bc[2] = rsqrtf(var + 1e-14f);
        }
    }
    __syncthreads();
    float mi = bc[0], mj = bc[1], inv = bc[2];
    float am = 0.f;
    for (int i = threadIdx.x; i < Nq; i += 1024) {
        float av = (si[i] - mi) * inv;
        float cv = (sj[i] - mj) * inv;
        g_a[b * Nq + i] = av;
        g_c[b * Nq + i] = cv;
        am = fmaxf(am, fabsf(av));
    }
    // reduce amax over block
    __syncthreads();
#pragma unroll
    for (int o = 16; o; o >>= 1) am = fmaxf(am, __shfl_xor_sync(~0u, am, o));
    if (lane == 0) red[0][w] = am;
    __syncthreads();
    if (threadIdx.x < 32) {
        float v = red[0][lane];
#pragma unroll
        for (int o = 16; o; o >>= 1) v = fmaxf(v, __shfl_xor_sync(~0u, v, o));
        if (lane == 0) g_amax[b] = v;
    }
    // reset global max-abs accumulators (any single thread; next kernel is stream-ordered)
    if (b == 0 && threadIdx.x == 0) { g_gmax_i = 0; g_bmax_i = 0; }
}

// ---------------- K2b: global max|gamma|, max|beta| -------------------------
__global__ void __launch_bounds__(256) k_gbmax(const float* __restrict__ gamma,
                                               const float* __restrict__ beta) {
    const float4* gp = (const float4*)gamma;
    const float4* bp = (const float4*)beta;
    const int n4 = Nq * Nq / 4;
    float gm = 0.f, bm = 0.f;
    for (int i = blockIdx.x * 256 + threadIdx.x; i < n4; i += gridDim.x * 256) {
        float4 g = gp[i], b = bp[i];
        gm = fmaxf(gm, fmaxf(fmaxf(fabsf(g.x), fabsf(g.y)), fmaxf(fabsf(g.z), fabsf(g.w))));
        bm = fmaxf(bm, fmaxf(fmaxf(fabsf(b.x), fabsf(b.y)), fmaxf(fabsf(b.z), fabsf(b.w))));
    }
    __shared__ float sg[32], sb[32];
    int w = threadIdx.x >> 5, lane = threadIdx.x & 31;
#pragma unroll
    for (int o = 16; o; o >>= 1) {
        gm = fmaxf(gm, __shfl_xor_sync(~0u, gm, o));
        bm = fmaxf(bm, __shfl_xor_sync(~0u, bm, o));
    }
    if (lane == 0) { sg[w] = gm; sb[w] = bm; }
    __syncthreads();
    if (threadIdx.x < 32) {
        float g = (lane < 8) ? sg[lane] : 0.f;
        float b = (lane < 8) ? sb[lane] : 0.f;
#pragma unroll
        for (int o = 4; o; o >>= 1) {
            g = fmaxf(g, __shfl_xor_sync(~0u, g, o));
            b = fmaxf(b, __shfl_xor_sync(~0u, b, o));
        }
        if (lane == 0) {
            atomicMax(&g_gmax_i, __float_as_int(g));   // positive floats: int order == float order
            atomicMax(&g_bmax_i, __float_as_int(b));
        }
    }
}

// ---------------- K3: single pass — exp with analytic bound, P write, S sum -
// blockIdx.x = jt*64 + isc*16 + b   (b fastest -> gamma tile L2-shared across batches)
__global__ void __launch_bounds__(256) k_exp(const float* __restrict__ gamma,
                                             const float* __restrict__ beta) {
    int b   = blockIdx.x & 15;
    int isc = (blockIdx.x >> 4) & 3;
    int jt  = blockIdx.x >> 6;
    int j = jt * 256 + threadIdx.x;
    __shared__ float ash[512];
    ash[threadIdx.x]       = g_a[b * Nq + isc * 512 + threadIdx.x];
    ash[threadIdx.x + 256] = g_a[b * Nq + isc * 512 + threadIdx.x + 256];
    __syncthreads();
    float cj = g_c[b * Nq + j];
    // analytic upper bound on column j's post-LeakyReLU max:
    // v = (a_i + c_j)*g + bt  =>  v <= (amax + |c_j|)*gmax + bmax ; leaky(v) <= max(v,0) <= bound
    float gmax = __int_as_float(g_gmax_i);
    float bmax = __int_as_float(g_bmax_i);
    float Mj = (g_amax[b] + fabsf(cj)) * gmax + bmax;
    const float* gp = gamma + (size_t)(isc * 512) * Nq + j;
    const float* bp = beta  + (size_t)(isc * 512) * Nq + j;
    __nv_bfloat16* pp = g_P + ((size_t)b * Nq + isc * 512) * Nq + j;
    float s = 0.f;
#pragma unroll 4
    for (int i = 0; i < 512; i++) {
        float g  = gp[(size_t)i * Nq];
        float bt = bp[(size_t)i * Nq];
        float v = fmaf(ash[i] + cj, g, bt);
        v = fmaxf(v, 0.2f * v);            // LeakyReLU(0.2)
        float e = __expf(v - Mj);
        s += e;
        pp[(size_t)i * Nq] = __float2bfloat16(e);
    }
    g_Spart[(isc * 16 + b) * Nq + j] = s;
}

// ---------------- K3b: combine i-chunk partial sums -> Zi -------------------
__global__ void __launch_bounds__(256) k_combine() {
    int idx = blockIdx.x * 256 + threadIdx.x;   // = b*Nq + j
    int b = idx >> 11, j = idx & (Nq - 1);
    float s = 0.f;
#pragma unroll
    for (int p = 0; p < 4; p++) s += g_Spart[(p * 16 + b) * Nq + j];
    g_Zi[idx] = 1.0f / s;
}

// ---------------- K4: fold Zi into x rows (in place, bf16) ------------------
// out = sum_j e[i,j] * (Zi[j] * x[j,:])
__global__ void __launch_bounds__(256) k_scalex() {
    int idx = blockIdx.x * 256 + threadIdx.x;   // one 8-elem chunk per thread
    int row   = idx >> 5;                       // Bq*Nq rows, 32 chunks of 8 per row
    int chunk = idx & 31;
    float zi = g_Zi[row];
    __nv_bfloat16* p = g_xbf + (size_t)row * Dq + chunk * 8;
    uint4 u = *(uint4*)p;
    __nv_bfloat162* h = (__nv_bfloat162*)&u;
#pragma unroll
    for (int k = 0; k < 4; k++) {
        float2 f = __bfloat1622float2(h[k]);
        h[k] = __floats2bfloat162_rn(f.x * zi, f.y * zi);
    }
    *(uint4*)p = u;
}

// ---------------- K5: batched GEMM out = P @ xbf, sigmoid epilogue ---------
// block tile 128x128, BK=32, 8 warps (4x2), mma.sync m16n8k16 bf16
#define PSTR 40    // padded smem stride for P tile rows (32 used + 8 pad) -> 80B
#define XSTR 136   // padded smem stride for x tile rows (128 used + 8 pad) -> 272B
__global__ void __launch_bounds__(256) k_gemm(float* __restrict__ out) {
    __shared__ __align__(16) __nv_bfloat16 ps[2][128 * PSTR];
    __shared__ __align__(16) __nv_bfloat16 xs[2][32 * XSTR];

    int b  = blockIdx.z;
    int m0 = blockIdx.x * 128;
    int n0 = blockIdx.y * 128;
    const __nv_bfloat16* Pg = g_P   + (size_t)b * Nq * Nq;
    const __nv_bfloat16* Xg = g_xbf + (size_t)b * Nq * Dq;

    int tid = threadIdx.x, lane = tid & 31, warp = tid >> 5;
    int wm = warp >> 1, wn = warp & 1;

    // loader indices
    int li1 = tid + 256;
    int rp0 = tid >> 2,  cp0 = (tid & 3) * 8;
    int rp1 = li1 >> 2,  cp1 = (li1 & 3) * 8;
    int rx0 = tid >> 4,  cx0 = (tid & 15) * 8;
    int rx1 = li1 >> 4,  cx1 = (li1 & 15) * 8;

    // ldmatrix lane address components
    int lr = (lane & 7) + ((lane >> 3) & 1) * 8;
    int lc = (lane >> 4) * 8;

    float acc[2][8][4];
#pragma unroll
    for (int mt = 0; mt < 2; mt++)
#pragma unroll
        for (int nt = 0; nt < 8; nt++)
#pragma unroll
            for (int q = 0; q < 4; q++) acc[mt][nt][q] = 0.f;

    // prologue: tile 0 -> buffer 0
    {
        uint4 pa = *(const uint4*)(Pg + (size_t)(m0 + rp0) * Nq + cp0);
        uint4 pb = *(const uint4*)(Pg + (size_t)(m0 + rp1) * Nq + cp1);
        uint4 xa = *(const uint4*)(Xg + (size_t)rx0 * Dq + n0 + cx0);
        uint4 xb = *(const uint4*)(Xg + (size_t)rx1 * Dq + n0 + cx1);
        *(uint4*)&ps[0][rp0 * PSTR + cp0] = pa;
        *(uint4*)&ps[0][rp1 * PSTR + cp1] = pb;
        *(uint4*)&xs[0][rx0 * XSTR + cx0] = xa;
        *(uint4*)&xs[0][rx1 * XSTR + cx1] = xb;
    }
    __syncthreads();

    for (int kt = 0; kt < Nq / 32; kt++) {
        int cur = kt & 1;
        bool more = (kt + 1) < (Nq / 32);
        uint4 pa, pb, xa, xb;
        if (more) {
            int kb = (kt + 1) * 32;
            pa = *(const uint4*)(Pg + (size_t)(m0 + rp0) * Nq + kb + cp0);
            pb = *(const uint4*)(Pg + (size_t)(m0 + rp1) * Nq + kb + cp1);
            xa = *(const uint4*)(Xg + (size_t)(kb + rx0) * Dq + n0 + cx0);
            xb = *(const uint4*)(Xg + (size_t)(kb + rx1) * Dq + n0 + cx1);
        }
#pragma unroll
        for (int ks = 0; ks < 2; ks++) {
            int kk = ks * 16;
            unsigned af[2][4];
#pragma unroll
            for (int mt = 0; mt < 2; mt++) {
                unsigned addr = (unsigned)__cvta_generic_to_shared(
                    &ps[cur][(wm * 32 + mt * 16 + lr) * PSTR + kk + lc]);
                asm volatile("ldmatrix.sync.aligned.m8n8.x4.shared.b16 {%0,%1,%2,%3}, [%4];"
                             : "=r"(af[mt][0]), "=r"(af[mt][1]), "=r"(af[mt][2]), "=r"(af[mt][3])
                             : "r"(addr));
            }
            unsigned bfr[8][2];
#pragma unroll
            for (int ng = 0; ng < 4; ng++) {
                unsigned addr = (unsigned)__cvta_generic_to_shared(
                    &xs[cur][(kk + lr) * XSTR + wn * 64 + ng * 16 + lc]);
                unsigned r0, r1, r2, r3;
                asm volatile("ldmatrix.sync.aligned.m8n8.x4.trans.shared.b16 {%0,%1,%2,%3}, [%4];"
                             : "=r"(r0), "=r"(r1), "=r"(r2), "=r"(r3)
                             : "r"(addr));
                bfr[2 * ng][0] = r0; bfr[2 * ng][1] = r1;
                bfr[2 * ng + 1][0] = r2; bfr[2 * ng + 1][1] = r3;
            }
#pragma unroll
            for (int mt = 0; mt < 2; mt++)
#pragma unroll
                for (int nt = 0; nt < 8; nt++)
                    asm volatile("mma.sync.aligned.m16n8k16.row.col.f32.bf16.bf16.f32 "
                                 "{%0,%1,%2,%3}, {%4,%5,%6,%7}, {%8,%9}, {%0,%1,%2,%3};"
                                 : "+f"(acc[mt][nt][0]), "+f"(acc[mt][nt][1]),
                                   "+f"(acc[mt][nt][2]), "+f"(acc[mt][nt][3])
                                 : "r"(af[mt][0]), "r"(af[mt][1]), "r"(af[mt][2]), "r"(af[mt][3]),
                                   "r"(bfr[nt][0]), "r"(bfr[nt][1]));
        }
        if (more) {
            // safe without an extra barrier: buffer `nxt` was last READ in
            // iteration kt-1, whose end-of-loop __syncthreads already ordered
            // those reads before these writes.
            int nxt = cur ^ 1;
            *(uint4*)&ps[nxt][rp0 * PSTR + cp0] = pa;
            *(uint4*)&ps[nxt][rp1 * PSTR + cp1] = pb;
            *(uint4*)&xs[nxt][rx0 * XSTR + cx0] = xa;
            *(uint4*)&xs[nxt][rx1 * XSTR + cx1] = xb;
        }
        __syncthreads();
    }

    // epilogue: sigmoid + store
#pragma unroll
    for (int mt = 0; mt < 2; mt++) {
        int row = m0 + wm * 32 + mt * 16 + (lane >> 2);
#pragma unroll
        for (int nt = 0; nt < 8; nt++) {
            int col = n0 + wn * 64 + nt * 8 + (lane & 3) * 2;
            float2 v0 = { sigf(acc[mt][nt][0]), sigf(acc[mt][nt][1]) };
            float2 v1 = { sigf(acc[mt][nt][2]), sigf(acc[mt][nt][3]) };
            *(float2*)(out + ((size_t)b * Nq + row)     * Dq + col) = v0;
            *(float2*)(out + ((size_t)b * Nq + row + 8) * Dq + col) = v1;
        }
    }
}

// ---------------- launch ---------------------------------------------------
extern "C" void kernel_launch(void* const* d_in, const int* in_sizes, int n_in,
                              void* d_out, int out_size) {
    const float* x     = (const float*)d_in[0];
    const float* w     = (const float*)d_in[1];
    const float* gamma = (const float*)d_in[2];
    const float* beta  = (const float*)d_in[3];
    float* out = (float*)d_out;

    k_proj<<<Bq * Nq / 8, 256>>>(x, w);
    k_stats<<<Bq, 1024>>>();                 // also resets g_gmax/g_bmax
    k_gbmax<<<512, 256>>>(gamma, beta);
    k_exp<<<512, 256>>>(gamma, beta);        // single gamma/beta pass: P + partial sums
    k_combine<<<Bq * Nq / 256, 256>>>();
    k_scalex<<<Bq * Nq * Dq / (256 * 8), 256>>>();
    dim3 g5(Nq / 128, Dq / 128, Bq);
    k_gemm<<<g5, 256>>>(out);
}

// round 14
// speedup vs baseline: 1.4763x; 1.1249x over previous
#include <cuda_runtime.h>
#include <cuda_bf16.h>
#include <math_constants.h>

#define Bq 16
#define Nq 2048
#define Dq 256

// ---------------- scratch (static device globals; no runtime allocation) ----
__device__ float g_si[Bq * Nq];
__device__ float g_sj[Bq * Nq];
__device__ float g_a[Bq * Nq];   // normalized row term
__device__ float g_c[Bq * Nq];   // normalized col term
__device__ float g_Spart[16 * Bq * Nq];
__device__ float g_Zi[Bq * Nq];  // 1/Z per column
__device__ float g_amax[Bq];     // per-batch max |a_i|
__device__ int   g_gmax_i;       // max |gamma| as int bits (positive floats)
__device__ int   g_bmax_i;       // max |beta|  as int bits
__device__ __nv_bfloat16 g_xbf[(size_t)Bq * Nq * Dq];
__device__ __nv_bfloat16 g_P[(size_t)Bq * Nq * Nq];

__device__ __forceinline__ float sigf(float v) {
    return 1.0f / (1.0f + __expf(-v));
}

// ---------------- K1: s_i, s_j projections + bf16 copy of x ----------------
// one warp per (b,n) row; block = 8 warps
__global__ void __launch_bounds__(256) k_proj(const float* __restrict__ x,
                                              const float* __restrict__ w) {
    __shared__ float ws[2 * Dq];
    for (int t = threadIdx.x; t < 2 * Dq; t += blockDim.x) ws[t] = w[t];
    __syncthreads();
    int warp = threadIdx.x >> 5, lane = threadIdx.x & 31;
    size_t row = (size_t)blockIdx.x * 8 + warp;   // < Bq*Nq
    const float4* xr = (const float4*)(x + row * Dq);
    float sj = 0.f, si = 0.f;
#pragma unroll
    for (int k = 0; k < 2; k++) {
        float4 v = xr[k * 32 + lane];
        int e = (k * 32 + lane) * 4;
        sj += v.x * ws[e] + v.y * ws[e + 1] + v.z * ws[e + 2] + v.w * ws[e + 3];
        si += v.x * ws[Dq + e] + v.y * ws[Dq + e + 1] + v.z * ws[Dq + e + 2] + v.w * ws[Dq + e + 3];
        __nv_bfloat162 p0 = __floats2bfloat162_rn(v.x, v.y);
        __nv_bfloat162 p1 = __floats2bfloat162_rn(v.z, v.w);
        *(__nv_bfloat162*)(g_xbf + row * Dq + e)     = p0;
        *(__nv_bfloat162*)(g_xbf + row * Dq + e + 2) = p1;
    }
#pragma unroll
    for (int o = 16; o; o >>= 1) {
        sj += __shfl_xor_sync(0xffffffffu, sj, o);
        si += __shfl_xor_sync(0xffffffffu, si, o);
    }
    if (lane == 0) { g_sj[row] = sj; g_si[row] = si; }
}

// ---------------- K2: per-batch LN stats (separable!) + normalize + amax ----
__global__ void __launch_bounds__(1024) k_stats() {
    int b = blockIdx.x;
    const float* si = g_si + b * Nq;
    const float* sj = g_sj + b * Nq;
    float s1 = 0, q1 = 0, s2 = 0, q2 = 0;
    for (int i = threadIdx.x; i < Nq; i += 1024) {
        float u = si[i], v = sj[i];
        s1 += u; q1 += u * u; s2 += v; q2 += v * v;
    }
    __shared__ float red[4][32];
    __shared__ float bc[3];
    int w = threadIdx.x >> 5, lane = threadIdx.x & 31;
#pragma unroll
    for (int o = 16; o; o >>= 1) {
        s1 += __shfl_xor_sync(~0u, s1, o);
        q1 += __shfl_xor_sync(~0u, q1, o);
        s2 += __shfl_xor_sync(~0u, s2, o);
        q2 += __shfl_xor_sync(~0u, q2, o);
    }
    if (lane == 0) { red[0][w] = s1; red[1][w] = q1; red[2][w] = s2; red[3][w] = q2; }
    __syncthreads();
    if (threadIdx.x < 32) {
        float v0 = red[0][lane], v1 = red[1][lane], v2 = red[2][lane], v3 = red[3][lane];
#pragma unroll
        for (int o = 16; o; o >>= 1) {
            v0 += __shfl_xor_sync(~0u, v0, o);
            v1 += __shfl_xor_sync(~0u, v1, o);
            v2 += __shfl_xor_sync(~0u, v2, o);
            v3 += __shfl_xor_sync(~0u, v3, o);
        }
        if (lane == 0) {
            float mi = v0 / (float)Nq, mj = v2 / (float)Nq;
            float var = (v1 / (float)Nq - mi * mi) + (v3 / (float)Nq - mj * mj);
            bc[0] = mi; bc[1] = mj; bc[2] = rsqrtf(var + 1e-14f);
        }
    }
    __syncthreads();
    float mi = bc[0], mj = bc[1], inv = bc[2];
    float am = 0.f;
    for (int i = threadIdx.x; i < Nq; i += 1024) {
        float av = (si[i] - mi) * inv;
        float cv = (sj[i] - mj) * inv;
        g_a[b * Nq + i] = av;
        g_c[b * Nq + i] = cv;
        am = fmaxf(am, fabsf(av));
    }
    // reduce amax over block
    __syncthreads();
#pragma unroll
    for (int o = 16; o; o >>= 1) am = fmaxf(am, __shfl_xor_sync(~0u, am, o));
    if (lane == 0) red[0][w] = am;
    __syncthreads();
    if (threadIdx.x < 32) {
        float v = red[0][lane];
#pragma unroll
        for (int o = 16; o; o >>= 1) v = fmaxf(v, __shfl_xor_sync(~0u, v, o));
        if (lane == 0) g_amax[b] = v;
    }
    // reset global max-abs accumulators (any single thread; next kernel is stream-ordered)
    if (b == 0 && threadIdx.x == 0) { g_gmax_i = 0; g_bmax_i = 0; }
}

// ---------------- K2b: global max|gamma|, max|beta| -------------------------
__global__ void __launch_bounds__(256) k_gbmax(const float* __restrict__ gamma,
                                               const float* __restrict__ beta) {
    const float4* gp = (const float4*)gamma;
    const float4* bp = (const float4*)beta;
    const int n4 = Nq * Nq / 4;
    float gm = 0.f, bm = 0.f;
    for (int i = blockIdx.x * 256 + threadIdx.x; i < n4; i += gridDim.x * 256) {
        float4 g = gp[i], b = bp[i];
        gm = fmaxf(gm, fmaxf(fmaxf(fabsf(g.x), fabsf(g.y)), fmaxf(fabsf(g.z), fabsf(g.w))));
        bm = fmaxf(bm, fmaxf(fmaxf(fabsf(b.x), fabsf(b.y)), fmaxf(fabsf(b.z), fabsf(b.w))));
    }
    __shared__ float sg[32], sb[32];
    int w = threadIdx.x >> 5, lane = threadIdx.x & 31;
#pragma unroll
    for (int o = 16; o; o >>= 1) {
        gm = fmaxf(gm, __shfl_xor_sync(~0u, gm, o));
        bm = fmaxf(bm, __shfl_xor_sync(~0u, bm, o));
    }
    if (lane == 0) { sg[w] = gm; sb[w] = bm; }
    __syncthreads();
    if (threadIdx.x < 32) {
        float g = (lane < 8) ? sg[lane] : 0.f;
        float b = (lane < 8) ? sb[lane] : 0.f;
#pragma unroll
        for (int o = 4; o; o >>= 1) {
            g = fmaxf(g, __shfl_xor_sync(~0u, g, o));
            b = fmaxf(b, __shfl_xor_sync(~0u, b, o));
        }
        if (lane == 0) {
            atomicMax(&g_gmax_i, __float_as_int(g));   // positive floats: int order == float order
            atomicMax(&g_bmax_i, __float_as_int(b));
        }
    }
}

// ---------------- K3: single pass — exp with analytic bound, P write, S sum -
// each thread: 2 adjacent j columns (float2 loads, bf16x2 store), 128-row i-chunk
// blockIdx.x = jt*256 + isc*16 + b  (b fastest -> gamma tile L2-shared across batches)
__global__ void __launch_bounds__(256) k_exp(const float* __restrict__ gamma,
                                             const float* __restrict__ beta) {
    int b   = blockIdx.x & 15;
    int isc = (blockIdx.x >> 4) & 15;
    int jt  = blockIdx.x >> 8;
    int j = jt * 512 + threadIdx.x * 2;
    __shared__ float ash[128];
    if (threadIdx.x < 128) ash[threadIdx.x] = g_a[b * Nq + isc * 128 + threadIdx.x];
    __syncthreads();
    float2 cj = *(const float2*)(g_c + b * Nq + j);
    // analytic upper bound on column j's post-LeakyReLU max:
    // v = (a_i + c_j)*g + bt  =>  v <= (amax + |c_j|)*gmax + bmax ; leaky(v) <= max(v,0) <= bound
    float gmax = __int_as_float(g_gmax_i);
    float bmax = __int_as_float(g_bmax_i);
    float am   = g_amax[b];
    float Mj0 = (am + fabsf(cj.x)) * gmax + bmax;
    float Mj1 = (am + fabsf(cj.y)) * gmax + bmax;
    const float2* gp = (const float2*)(gamma + (size_t)(isc * 128) * Nq + j);
    const float2* bp = (const float2*)(beta  + (size_t)(isc * 128) * Nq + j);
    __nv_bfloat162* pp = (__nv_bfloat162*)(g_P + ((size_t)b * Nq + isc * 128) * Nq + j);
    float s0 = 0.f, s1 = 0.f;
#pragma unroll 4
    for (int i = 0; i < 128; i++) {
        float2 g  = gp[(size_t)i * (Nq / 2)];
        float2 bt = bp[(size_t)i * (Nq / 2)];
        float ai = ash[i];
        float v0 = fmaf(ai + cj.x, g.x, bt.x);
        float v1 = fmaf(ai + cj.y, g.y, bt.y);
        v0 = fmaxf(v0, 0.2f * v0);          // LeakyReLU(0.2)
        v1 = fmaxf(v1, 0.2f * v1);
        float e0 = __expf(v0 - Mj0);
        float e1 = __expf(v1 - Mj1);
        s0 += e0; s1 += e1;
        pp[(size_t)i * (Nq / 2)] = __floats2bfloat162_rn(e0, e1);
    }
    *(float2*)(g_Spart + (size_t)(isc * 16 + b) * Nq + j) = make_float2(s0, s1);
}

// ---------------- K3b: combine i-chunk partial sums -> Zi -------------------
__global__ void __launch_bounds__(256) k_combine() {
    int idx = blockIdx.x * 256 + threadIdx.x;   // = b*Nq + j
    int b = idx >> 11, j = idx & (Nq - 1);
    float s = 0.f;
#pragma unroll
    for (int p = 0; p < 16; p++) s += g_Spart[(size_t)(p * 16 + b) * Nq + j];
    g_Zi[idx] = 1.0f / s;
}

// ---------------- K4: fold Zi into x rows (in place, bf16) ------------------
// out = sum_j e[i,j] * (Zi[j] * x[j,:])
__global__ void __launch_bounds__(256) k_scalex() {
    int idx = blockIdx.x * 256 + threadIdx.x;   // one 8-elem chunk per thread
    int row   = idx >> 5;                       // Bq*Nq rows, 32 chunks of 8 per row
    int chunk = idx & 31;
    float zi = g_Zi[row];
    __nv_bfloat16* p = g_xbf + (size_t)row * Dq + chunk * 8;
    uint4 u = *(uint4*)p;
    __nv_bfloat162* h = (__nv_bfloat162*)&u;
#pragma unroll
    for (int k = 0; k < 4; k++) {
        float2 f = __bfloat1622float2(h[k]);
        h[k] = __floats2bfloat162_rn(f.x * zi, f.y * zi);
    }
    *(uint4*)p = u;
}

// ---------------- K5: batched GEMM out = P @ xbf, sigmoid epilogue ---------
// block tile 128x128, BK=32, 8 warps (4x2), mma.sync m16n8k16 bf16
#define PSTR 40    // padded smem stride for P tile rows (32 used + 8 pad) -> 80B
#define XSTR 136   // padded smem stride for x tile rows (128 used + 8 pad) -> 272B
__global__ void __launch_bounds__(256) k_gemm(float* __restrict__ out) {
    __shared__ __align__(16) __nv_bfloat16 ps[2][128 * PSTR];
    __shared__ __align__(16) __nv_bfloat16 xs[2][32 * XSTR];

    int b  = blockIdx.z;
    int m0 = blockIdx.x * 128;
    int n0 = blockIdx.y * 128;
    const __nv_bfloat16* Pg = g_P   + (size_t)b * Nq * Nq;
    const __nv_bfloat16* Xg = g_xbf + (size_t)b * Nq * Dq;

    int tid = threadIdx.x, lane = tid & 31, warp = tid >> 5;
    int wm = warp >> 1, wn = warp & 1;

    // loader indices
    int li1 = tid + 256;
    int rp0 = tid >> 2,  cp0 = (tid & 3) * 8;
    int rp1 = li1 >> 2,  cp1 = (li1 & 3) * 8;
    int rx0 = tid >> 4,  cx0 = (tid & 15) * 8;
    int rx1 = li1 >> 4,  cx1 = (li1 & 15) * 8;

    // ldmatrix lane address components
    int lr = (lane & 7) + ((lane >> 3) & 1) * 8;
    int lc = (lane >> 4) * 8;

    float acc[2][8][4];
#pragma unroll
    for (int mt = 0; mt < 2; mt++)
#pragma unroll
        for (int nt = 0; nt < 8; nt++)
#pragma unroll
            for (int q = 0; q < 4; q++) acc[mt][nt][q] = 0.f;

    // prologue: tile 0 -> buffer 0
    {
        uint4 pa = *(const uint4*)(Pg + (size_t)(m0 + rp0) * Nq + cp0);
        uint4 pb = *(const uint4*)(Pg + (size_t)(m0 + rp1) * Nq + cp1);
        uint4 xa = *(const uint4*)(Xg + (size_t)rx0 * Dq + n0 + cx0);
        uint4 xb = *(const uint4*)(Xg + (size_t)rx1 * Dq + n0 + cx1);
        *(uint4*)&ps[0][rp0 * PSTR + cp0] = pa;
        *(uint4*)&ps[0][rp1 * PSTR + cp1] = pb;
        *(uint4*)&xs[0][rx0 * XSTR + cx0] = xa;
        *(uint4*)&xs[0][rx1 * XSTR + cx1] = xb;
    }
    __syncthreads();

    for (int kt = 0; kt < Nq / 32; kt++) {
        int cur = kt & 1;
        bool more = (kt + 1) < (Nq / 32);
        uint4 pa, pb, xa, xb;
        if (more) {
            int kb = (kt + 1) * 32;
            pa = *(const uint4*)(Pg + (size_t)(m0 + rp0) * Nq + kb + cp0);
            pb = *(const uint4*)(Pg + (size_t)(m0 + rp1) * Nq + kb + cp1);
            xa = *(const uint4*)(Xg + (size_t)(kb + rx0) * Dq + n0 + cx0);
            xb = *(const uint4*)(Xg + (size_t)(kb + rx1) * Dq + n0 + cx1);
        }
#pragma unroll
        for (int ks = 0; ks < 2; ks++) {
            int kk = ks * 16;
            unsigned af[2][4];
#pragma unroll
            for (int mt = 0; mt < 2; mt++) {
                unsigned addr = (unsigned)__cvta_generic_to_shared(
                    &ps[cur][(wm * 32 + mt * 16 + lr) * PSTR + kk + lc]);
                asm volatile("ldmatrix.sync.aligned.m8n8.x4.shared.b16 {%0,%1,%2,%3}, [%4];"
                             : "=r"(af[mt][0]), "=r"(af[mt][1]), "=r"(af[mt][2]), "=r"(af[mt][3])
                             : "r"(addr));
            }
            unsigned bfr[8][2];
#pragma unroll
            for (int ng = 0; ng < 4; ng++) {
                unsigned addr = (unsigned)__cvta_generic_to_shared(
                    &xs[cur][(kk + lr) * XSTR + wn * 64 + ng * 16 + lc]);
                unsigned r0, r1, r2, r3;
                asm volatile("ldmatrix.sync.aligned.m8n8.x4.trans.shared.b16 {%0,%1,%2,%3}, [%4];"
                             : "=r"(r0), "=r"(r1), "=r"(r2), "=r"(r3)
                             : "r"(addr));
                bfr[2 * ng][0] = r0; bfr[2 * ng][1] = r1;
                bfr[2 * ng + 1][0] = r2; bfr[2 * ng + 1][1] = r3;
            }
#pragma unroll
            for (int mt = 0; mt < 2; mt++)
#pragma unroll
                for (int nt = 0; nt < 8; nt++)
                    asm volatile("mma.sync.aligned.m16n8k16.row.col.f32.bf16.bf16.f32 "
                                 "{%0,%1,%2,%3}, {%4,%5,%6,%7}, {%8,%9}, {%0,%1,%2,%3};"
                                 : "+f"(acc[mt][nt][0]), "+f"(acc[mt][nt][1]),
                                   "+f"(acc[mt][nt][2]), "+f"(acc[mt][nt][3])
                                 : "r"(af[mt][0]), "r"(af[mt][1]), "r"(af[mt][2]), "r"(af[mt][3]),
                                   "r"(bfr[nt][0]), "r"(bfr[nt][1]));
        }
        if (more) {
            // safe without an extra barrier: buffer `nxt` was last READ in
            // iteration kt-1, whose end-of-loop __syncthreads already ordered
            // those reads before these writes.
            int nxt = cur ^ 1;
            *(uint4*)&ps[nxt][rp0 * PSTR + cp0] = pa;
            *(uint4*)&ps[nxt][rp1 * PSTR + cp1] = pb;
            *(uint4*)&xs[nxt][rx0 * XSTR + cx0] = xa;
            *(uint4*)&xs[nxt][rx1 * XSTR + cx1] = xb;
        }
        __syncthreads();
    }

    // epilogue: sigmoid + store
#pragma unroll
    for (int mt = 0; mt < 2; mt++) {
        int row = m0 + wm * 32 + mt * 16 + (lane >> 2);
#pragma unroll
        for (int nt = 0; nt < 8; nt++) {
            int col = n0 + wn * 64 + nt * 8 + (lane & 3) * 2;
            float2 v0 = { sigf(acc[mt][nt][0]), sigf(acc[mt][nt][1]) };
            float2 v1 = { sigf(acc[mt][nt][2]), sigf(acc[mt][nt][3]) };
            *(float2*)(out + ((size_t)b * Nq + row)     * Dq + col) = v0;
            *(float2*)(out + ((size_t)b * Nq + row + 8) * Dq + col) = v1;
        }
    }
}

// ---------------- launch ---------------------------------------------------
extern "C" void kernel_launch(void* const* d_in, const int* in_sizes, int n_in,
                              void* d_out, int out_size) {
    const float* x     = (const float*)d_in[0];
    const float* w     = (const float*)d_in[1];
    const float* gamma = (const float*)d_in[2];
    const float* beta  = (const float*)d_in[3];
    float* out = (float*)d_out;

    k_proj<<<Bq * Nq / 8, 256>>>(x, w);
    k_stats<<<Bq, 1024>>>();                 // also resets g_gmax/g_bmax
    k_gbmax<<<512, 256>>>(gamma, beta);
    k_exp<<<1024, 256>>>(gamma, beta);       // single gamma/beta pass: P + partial sums
    k_combine<<<Bq * Nq / 256, 256>>>();
    k_scalex<<<Bq * Nq * Dq / (256 * 8), 256>>>();
    dim3 g5(Nq / 128, Dq / 128, Bq);
    k_gemm<<<g5, 256>>>(out);
}